// round 8
// baseline (speedup 1.0000x reference)
#include <cuda_runtime.h>
#include <cuda_bf16.h>

#define SQ 2048
#define DM 1024
#define NH 16
#define DKH 64
#define NHID 1024

typedef unsigned int u32;
typedef unsigned short u16;

// ---------------- scratch planes (bf16 hi/lo) ----------------
__device__ u16 g_xh[3*SQ*DM];        // split activations
__device__ u16 g_xl[3*SQ*DM];
__device__ u16 g_wth[3*NH*DKH*DM];   // split transposed QKV weights [(which*16+h)*64+k][d]
__device__ u16 g_wtl[3*NH*DKH*DM];
__device__ u16 g_woth[NHID*DM];      // split transposed Wo [n][k]
__device__ u16 g_wotl[NHID*DM];
__device__ u16 g_qh[NH*SQ*DKH];
__device__ u16 g_ql[NH*SQ*DKH];
__device__ u16 g_kh[NH*SQ*DKH];
__device__ u16 g_kl[NH*SQ*DKH];
__device__ u16 g_vth[NH*DKH*SQ];     // [h][d][s]
__device__ u16 g_vtl[NH*DKH*SQ];
__device__ u16 g_ch[SQ*NHID];
__device__ u16 g_cl[SQ*NHID];

// ---------------- helpers ----------------
__device__ __forceinline__ void split1(float x, u16& h, u16& l) {
    __nv_bfloat16 hb = __float2bfloat16(x);
    h = __bfloat16_as_ushort(hb);
    l = __bfloat16_as_ushort(__float2bfloat16(x - __bfloat162float(hb)));
}
__device__ __forceinline__ void split_pack(float x0, float x1, u32& h, u32& l) {
    u16 h0,l0,h1,l1;
    split1(x0,h0,l0); split1(x1,h1,l1);
    h = ((u32)h1<<16)|h0; l = ((u32)l1<<16)|l0;
}
__device__ __forceinline__ void mma_bf16(float* c, const u32* a, const u32* b) {
    asm volatile(
      "mma.sync.aligned.m16n8k16.row.col.f32.bf16.bf16.f32 "
      "{%0,%1,%2,%3}, {%4,%5,%6,%7}, {%8,%9}, {%0,%1,%2,%3};\n"
      : "+f"(c[0]), "+f"(c[1]), "+f"(c[2]), "+f"(c[3])
      : "r"(a[0]), "r"(a[1]), "r"(a[2]), "r"(a[3]), "r"(b[0]), "r"(b[1]));
}
__device__ __forceinline__ void mma3(float* c, const u32* ah, const u32* al,
                                     const u32* bh, const u32* bl) {
    mma_bf16(c, ah, bh);
    mma_bf16(c, ah, bl);
    mma_bf16(c, al, bh);
}
__device__ __forceinline__ void cp16(u32 dst_smem, const void* src) {
    asm volatile("cp.async.cg.shared.global [%0], [%1], 16;\n"
                 :: "r"(dst_smem), "l"(src));
}
__device__ __forceinline__ void cp_commit() {
    asm volatile("cp.async.commit_group;\n");
}
template<int N> __device__ __forceinline__ void cp_wait() {
    asm volatile("cp.async.wait_group %0;\n" :: "n"(N));
}
__device__ __forceinline__ void ldsm4(u32& r0, u32& r1, u32& r2, u32& r3, u32 saddr) {
    asm volatile("ldmatrix.sync.aligned.m8n8.x4.shared.b16 {%0,%1,%2,%3}, [%4];\n"
                 : "=r"(r0), "=r"(r1), "=r"(r2), "=r"(r3) : "r"(saddr));
}

// ---------------------------------------------------------------------------
// Pre-pass 1: split activations (Q|K|V) -> bf16 hi/lo planes.
// ---------------------------------------------------------------------------
__global__ __launch_bounds__(256) void asplit_kernel(
    const float* __restrict__ Q, const float* __restrict__ K,
    const float* __restrict__ V, u16* __restrict__ oh, u16* __restrict__ ol)
{
    size_t base = ((size_t)blockIdx.x*256 + threadIdx.x)*8;
    int which = (int)(base >> 21);
    size_t rem = base & 2097151;
    const float* in = (which==0)?Q:(which==1)?K:V;
    float4 f0 = *(const float4*)(in+rem);
    float4 f1 = *(const float4*)(in+rem+4);
    u32 h0,l0,h1,l1,h2,l2,h3,l3;
    split_pack(f0.x,f0.y,h0,l0);
    split_pack(f0.z,f0.w,h1,l1);
    split_pack(f1.x,f1.y,h2,l2);
    split_pack(f1.z,f1.w,h3,l3);
    *(uint4*)(oh + base) = make_uint4(h0,h1,h2,h3);
    *(uint4*)(ol + base) = make_uint4(l0,l1,l2,l3);
}

// ---------------------------------------------------------------------------
// Pre-pass 2: transpose+split QKV weights -> [(which*16+h)*64 + k][d]
// ---------------------------------------------------------------------------
__global__ void wsplit_qkv_kernel(
    const float* __restrict__ Wq, const float* __restrict__ Wk,
    const float* __restrict__ Wv, u16* __restrict__ oh, u16* __restrict__ ol)
{
    __shared__ float t[32][33];
    int z = blockIdx.z, which = z>>4, h = z&15;
    const float* in = ((which==0)?Wq:(which==1)?Wk:Wv) + (size_t)h*DM*DKH;
    int d0 = blockIdx.x*32, k0 = blockIdx.y*32;
    int tx = threadIdx.x, ty = threadIdx.y;
    t[ty][tx] = in[(size_t)(d0+ty)*DKH + k0+tx];
    __syncthreads();
    float v = t[tx][ty];
    u16 hh,ll; split1(v,hh,ll);
    size_t o = ((size_t)z*DKH + k0+ty)*DM + d0+tx;
    oh[o]=hh; ol[o]=ll;
}

// Pre-pass 3: transpose+split Wo -> [n][k]
__global__ void wsplit_wo_kernel(
    const float* __restrict__ Wo, u16* __restrict__ oh, u16* __restrict__ ol)
{
    __shared__ float t[32][33];
    int k0 = blockIdx.x*32, n0 = blockIdx.y*32;
    int tx = threadIdx.x, ty = threadIdx.y;
    t[ty][tx] = Wo[(size_t)(k0+ty)*DM + n0+tx];
    __syncthreads();
    float v = t[tx][ty];
    u16 hh,ll; split1(v,hh,ll);
    size_t o = ((size_t)(n0+ty))*DM + k0+tx;
    oh[o]=hh; ol[o]=ll;
}

// ---------------------------------------------------------------------------
// proj4: fused QKV projection, 128(M) x 128(N = 2 heads) tiles, BK=32,
// two-stage cp.async, LDSM, 2 CTAs/SM.
// smem stage: Ah[128][20w] Al Bh[128][20w] Bl  (16 data words + 4 pad / row)
// ---------------------------------------------------------------------------
#define PAS 20
#define PTILE (128*PAS)          // 2560 words
#define PSTG (4*PTILE)           // 10240 words per stage
#define PROJ_SMEM (2*PSTG*4)     // 81920 B

__global__ __launch_bounds__(256,2) void proj4_kernel(
    const u32* __restrict__ Xh, const u32* __restrict__ Xl,
    const u32* __restrict__ Wth, const u32* __restrict__ Wtl,
    const float* __restrict__ bq, const float* __restrict__ bk,
    const float* __restrict__ bv,
    u16* __restrict__ oqh, u16* __restrict__ oql,
    u16* __restrict__ okh, u16* __restrict__ okl,
    u16* __restrict__ ovh, u16* __restrict__ ovl)
{
    extern __shared__ u32 sm[];
    const u32 smb = (u32)__cvta_generic_to_shared(sm);
    const int tid = threadIdx.x, lane = tid&31, wid = tid>>5;
    const int g = lane>>2, t4 = lane&3;
    const int wm = wid>>2, wn = wid&3;      // 2 x 4 warp grid, warp tile 64x32
    const int which = blockIdx.z, head0 = blockIdx.x*2, m0 = blockIdx.y*128;

    const u32* aH = Xh + (size_t)which*(SQ*DM/2);
    const u32* aL = Xl + (size_t)which*(SQ*DM/2);
    const int zrow = (which*NH + head0)*DKH;   // 128 weight rows

    float acc[4][4][4];
#pragma unroll
    for (int i=0;i<4;i++)
#pragma unroll
      for (int j=0;j<4;j++)
#pragma unroll
        for (int e=0;e<4;e++) acc[i][j][e]=0.f;

    auto issue = [&](int kt, int st){
        int k0w = kt*16;
        u32 base = st*PSTG;
#pragma unroll
        for (int j=0;j<8;j++){
            int i = tid + j*256;
            int tile = i>>9, rem = i&511;
            int r = rem>>2, c = rem&3;
            const u32* src;
            if      (tile==0) src = aH  + (size_t)(m0+r)*512   + k0w + c*4;
            else if (tile==1) src = aL  + (size_t)(m0+r)*512   + k0w + c*4;
            else if (tile==2) src = Wth + (size_t)(zrow+r)*512 + k0w + c*4;
            else              src = Wtl + (size_t)(zrow+r)*512 + k0w + c*4;
            cp16(smb + (base + tile*PTILE + r*PAS + c*4)*4, src);
        }
        cp_commit();
    };

    issue(0,0);
    for (int kt=0; kt<32; kt++){
        int st = kt&1;
        if (kt+1 < 32){ issue(kt+1, st^1); cp_wait<1>(); }
        else cp_wait<0>();
        __syncthreads();

        u32 base = st*PSTG;
#pragma unroll
        for (int ks=0; ks<2; ks++){
            // hold B fragments (32 cols) in regs
            u32 bh[2][4], bl[2][4];
#pragma unroll
            for (int p=0;p<2;p++){
                int nb = wn*32 + p*16 + ((lane>>4)<<3) + (lane&7);
                u32 w = base + 2*PTILE + nb*PAS + ks*8 + ((lane>>3)&1)*4;
                ldsm4(bh[p][0],bh[p][1],bh[p][2],bh[p][3], smb + w*4);
                ldsm4(bl[p][0],bl[p][1],bl[p][2],bl[p][3], smb + (w+PTILE)*4);
            }
#pragma unroll
            for (int i=0;i<4;i++){
                int rowb = wm*64 + i*16 + (lane&15);
                u32 w = base + rowb*PAS + ks*8 + (lane>>4)*4;
                u32 ah[4], al[4];
                ldsm4(ah[0],ah[1],ah[2],ah[3], smb + w*4);
                ldsm4(al[0],al[1],al[2],al[3], smb + (w+PTILE)*4);
#pragma unroll
                for (int p=0;p<2;p++){
                    mma3(acc[i][2*p  ], ah, al, bh[p]+0, bl[p]+0);
                    mma3(acc[i][2*p+1], ah, al, bh[p]+2, bl[p]+2);
                }
            }
        }
        __syncthreads();
    }

    // epilogue
    const float* bias = (which==0)?bq:(which==1)?bk:bv;
    const int transposed = (which==2);
    const float osc = (which==0)?0.125f:1.f;
#pragma unroll
    for (int i=0;i<4;i++){
#pragma unroll
        for (int j=0;j<4;j++){
            int r0 = m0 + wm*64 + i*16 + g;
            int r1 = r0 + 8;
            int ncol = wn*32 + j*8 + t4*2;
            int head = head0 + (ncol>>6);
            int dc = ncol & 63;
            float b0f = bias[head*DKH + dc];
            float b1f = bias[head*DKH + dc + 1];
            float v0 = (acc[i][j][0] + b0f) * osc;
            float v1 = (acc[i][j][1] + b1f) * osc;
            float v2 = (acc[i][j][2] + b0f) * osc;
            float v3 = (acc[i][j][3] + b1f) * osc;
            if (!transposed) {
                u16* outH = (which==0)?oqh:okh;
                u16* outL = (which==0)?oql:okl;
                u32 h,l;
                split_pack(v0,v1,h,l);
                ((u32*)outH)[(head*SQ + r0)*32 + (dc>>1)] = h;
                ((u32*)outL)[(head*SQ + r0)*32 + (dc>>1)] = l;
                split_pack(v2,v3,h,l);
                ((u32*)outH)[(head*SQ + r1)*32 + (dc>>1)] = h;
                ((u32*)outL)[(head*SQ + r1)*32 + (dc>>1)] = l;
            } else {
                u16 h,l;
                split1(v0,h,l); ovh[(head*DKH+dc  )*SQ + r0]=h; ovl[(head*DKH+dc  )*SQ + r0]=l;
                split1(v1,h,l); ovh[(head*DKH+dc+1)*SQ + r0]=h; ovl[(head*DKH+dc+1)*SQ + r0]=l;
                split1(v2,h,l); ovh[(head*DKH+dc  )*SQ + r1]=h; ovl[(head*DKH+dc  )*SQ + r1]=l;
                split1(v3,h,l); ovh[(head*DKH+dc+1)*SQ + r1]=h; ovl[(head*DKH+dc+1)*SQ + r1]=l;
            }
        }
    }
}

// ---------------------------------------------------------------------------
// Output projection (round-6 proven version): 128x64 tiles, BK=64.
// ---------------------------------------------------------------------------
#define GAS 36
#define A_WORDS (128*GAS)
#define B_WORDS (64*GAS)
#define GSTG (2*A_WORDS + 2*B_WORDS)
#define GEMM_SMEM (2*GSTG*4)

__global__ __launch_bounds__(256) void out2_kernel(
    const u32* __restrict__ Ah, const u32* __restrict__ Al,
    const u32* __restrict__ Bh, const u32* __restrict__ Bl,
    const float* __restrict__ bias, float* __restrict__ C)
{
    extern __shared__ u32 sm[];
    const u32 smb = (u32)__cvta_generic_to_shared(sm);
    const int tid=threadIdx.x, lane=tid&31, wid=tid>>5;
    const int g=lane>>2, t4=lane&3;
    const int wm=wid>>1, wn=wid&1;
    const int n0=blockIdx.x*64, m0=blockIdx.y*128;

    float acc[2][4][4];
#pragma unroll
    for (int i=0;i<2;i++)
#pragma unroll
      for (int j=0;j<4;j++)
#pragma unroll
        for (int e=0;e<4;e++) acc[i][j][e]=0.f;

    auto issue = [&](int kt, int st){
        int k0w = kt*32;
        u32 base = st*GSTG;
#pragma unroll
        for (int j=0;j<8;j++){
            int i = tid + j*256;
            int pl = i>>10, rem = i&1023;
            int r = rem>>3, c = rem&7;
            const u32* src = (pl? Al : Ah) + (size_t)(m0+r)*512 + k0w + c*4;
            cp16(smb + (base + pl*A_WORDS + r*GAS + c*4)*4, src);
        }
#pragma unroll
        for (int j=0;j<4;j++){
            int i = tid + j*256;
            int pl = i>>9, rem = i&511;
            int r = rem>>3, c = rem&7;
            const u32* src = (pl? Bl : Bh) + (size_t)(n0+r)*512 + k0w + c*4;
            cp16(smb + (base + 2*A_WORDS + pl*B_WORDS + r*GAS + c*4)*4, src);
        }
        cp_commit();
    };

    issue(0,0);
    for (int kt=0; kt<16; kt++){
        int st = kt&1;
        if (kt+1 < 16){ issue(kt+1, st^1); cp_wait<1>(); }
        else cp_wait<0>();
        __syncthreads();

        u32 base = st*GSTG;
#pragma unroll
        for (int ks=0;ks<4;ks++){
            u32 ah[2][4], al[2][4];
#pragma unroll
            for (int i=0;i<2;i++){
                int rowb = wm*32 + i*16 + (lane&15);
                u32 w = base + rowb*GAS + ks*8 + (lane>>4)*4;
                ldsm4(ah[i][0],ah[i][1],ah[i][2],ah[i][3], smb + w*4);
                ldsm4(al[i][0],al[i][1],al[i][2],al[i][3], smb + (w+A_WORDS)*4);
            }
#pragma unroll
            for (int p=0;p<2;p++){
                int nb = wn*32 + p*16 + ((lane>>4)<<3) + (lane&7);
                u32 w = base + 2*A_WORDS + nb*GAS + ks*8 + ((lane>>3)&1)*4;
                u32 bh[4], bl[4];
                ldsm4(bh[0],bh[1],bh[2],bh[3], smb + w*4);
                ldsm4(bl[0],bl[1],bl[2],bl[3], smb + (w+B_WORDS)*4);
#pragma unroll
                for (int i=0;i<2;i++){
                    mma3(acc[i][2*p  ], ah[i], al[i], bh+0, bl+0);
                    mma3(acc[i][2*p+1], ah[i], al[i], bh+2, bl+2);
                }
            }
        }
        __syncthreads();
    }

#pragma unroll
    for (int i=0;i<2;i++){
#pragma unroll
        for (int j=0;j<4;j++){
            int r0 = m0 + wm*32 + i*16 + g;
            int r1 = r0 + 8;
            int col = n0 + wn*32 + j*8 + t4*2;
            C[(size_t)r0*DM + col    ] = acc[i][j][0] + bias[col];
            C[(size_t)r0*DM + col + 1] = acc[i][j][1] + bias[col+1];
            C[(size_t)r1*DM + col    ] = acc[i][j][2] + bias[col];
            C[(size_t)r1*DM + col + 1] = acc[i][j][3] + bias[col+1];
        }
    }
}

// ---------------------------------------------------------------------------
// Flash attention (round-6 proven): cp.async double buffer, LDSM, 2 CTAs/SM
// ---------------------------------------------------------------------------
#define AS 36
#define KVW (64*AS)
#define ATTN_WORDS (2*128*AS + 2*4*KVW)
#define ATTN_SMEM (ATTN_WORDS*4)

__global__ __launch_bounds__(256,2) void attn_kernel(
    const u32* __restrict__ Qh, const u32* __restrict__ Ql,
    const u32* __restrict__ Kh, const u32* __restrict__ Kl,
    const u32* __restrict__ Vh, const u32* __restrict__ Vl,
    u16* __restrict__ Ch, u16* __restrict__ Cl)
{
    extern __shared__ u32 sm[];
    const u32 smb = (u32)__cvta_generic_to_shared(sm);

    const int tid = threadIdx.x, lane = tid&31, wid = tid>>5;
    const int g = lane>>2, t4 = lane&3;
    const int h = blockIdx.y, q0 = blockIdx.x*128;
    const int row = wid*16;

#pragma unroll
    for (int j=0;j<8;j++){
        int i = tid + j*256;
        int plane = i>>10, rem = i&1023;
        int r = rem>>3, c = rem&7;
        const u32* src = (plane ? Ql : Qh) + ((size_t)(h*SQ + q0 + r))*32 + c*4;
        cp16(smb + ((plane ? 128*AS : 0) + r*AS + c*4)*4, src);
    }
    cp_commit();

    auto issueKV = [&](int t, int st){
        u32 base = 2*128*AS + st*4*KVW;
#pragma unroll
        for (int j=0;j<2;j++){
            int i = tid + j*256;
            int r = i>>3, c = i&7;
            cp16(smb + (base +           r*AS + c*4)*4, Kh + ((size_t)(h*SQ + t*64 + r))*32 + c*4);
            cp16(smb + (base +   KVW +   r*AS + c*4)*4, Kl + ((size_t)(h*SQ + t*64 + r))*32 + c*4);
            cp16(smb + (base + 2*KVW +   r*AS + c*4)*4, Vh + ((size_t)(h*DKH + r))*1024 + t*32 + c*4);
            cp16(smb + (base + 3*KVW +   r*AS + c*4)*4, Vl + ((size_t)(h*DKH + r))*1024 + t*32 + c*4);
        }
        cp_commit();
    };
    issueKV(0,0);

    float oacc[8][4];
#pragma unroll
    for (int j=0;j<8;j++)
#pragma unroll
        for (int e=0;e<4;e++) oacc[j][e]=0.f;
    float m0r=-1e30f, m1r=-1e30f, l0r=0.f, l1r=0.f;

    for (int t=0; t<SQ/64; t++){
        const int st = t & 1;
        if (t+1 < SQ/64) { issueKV(t+1, st^1); cp_wait<1>(); }
        else cp_wait<0>();
        __syncthreads();

        u32 kbase = 2*128*AS + st*4*KVW;
        u32 vbase = kbase + 2*KVW;

        float sc[8][4];
#pragma unroll
        for (int j=0;j<8;j++)
#pragma unroll
            for (int e=0;e<4;e++) sc[j][e]=0.f;
#pragma unroll
        for (int ks=0;ks<4;ks++){
            u32 qh[4], ql[4];
            int rowb = row + (lane&15);
            u32 wq = rowb*AS + ks*8 + (lane>>4)*4;
            ldsm4(qh[0],qh[1],qh[2],qh[3], smb + wq*4);
            ldsm4(ql[0],ql[1],ql[2],ql[3], smb + (wq + 128*AS)*4);
#pragma unroll
            for (int p=0;p<4;p++){
                int nb = p*16 + ((lane>>4)<<3) + (lane&7);
                u32 w = kbase + nb*AS + ks*8 + ((lane>>3)&1)*4;
                u32 bh[4], bl[4];
                ldsm4(bh[0],bh[1],bh[2],bh[3], smb + w*4);
                ldsm4(bl[0],bl[1],bl[2],bl[3], smb + (w+KVW)*4);
                mma3(sc[2*p  ], qh, ql, bh+0, bl+0);
                mma3(sc[2*p+1], qh, ql, bh+2, bl+2);
            }
        }

        float tm0=-1e30f, tm1=-1e30f;
#pragma unroll
        for (int j=0;j<8;j++){
            tm0 = fmaxf(tm0, fmaxf(sc[j][0], sc[j][1]));
            tm1 = fmaxf(tm1, fmaxf(sc[j][2], sc[j][3]));
        }
        tm0 = fmaxf(tm0, __shfl_xor_sync(0xffffffffu, tm0, 1));
        tm0 = fmaxf(tm0, __shfl_xor_sync(0xffffffffu, tm0, 2));
        tm1 = fmaxf(tm1, __shfl_xor_sync(0xffffffffu, tm1, 1));
        tm1 = fmaxf(tm1, __shfl_xor_sync(0xffffffffu, tm1, 2));
        float mn0 = fmaxf(m0r, tm0), mn1 = fmaxf(m1r, tm1);
        float c0 = __expf(m0r - mn0), c1 = __expf(m1r - mn1);
        float rs0=0.f, rs1=0.f;
#pragma unroll
        for (int j=0;j<8;j++){
            sc[j][0]=__expf(sc[j][0]-mn0); sc[j][1]=__expf(sc[j][1]-mn0);
            sc[j][2]=__expf(sc[j][2]-mn1); sc[j][3]=__expf(sc[j][3]-mn1);
            rs0 += sc[j][0]+sc[j][1]; rs1 += sc[j][2]+sc[j][3];
        }
        rs0 += __shfl_xor_sync(0xffffffffu, rs0, 1);
        rs0 += __shfl_xor_sync(0xffffffffu, rs0, 2);
        rs1 += __shfl_xor_sync(0xffffffffu, rs1, 1);
        rs1 += __shfl_xor_sync(0xffffffffu, rs1, 2);
        l0r = l0r*c0 + rs0; l1r = l1r*c1 + rs1;
        m0r = mn0; m1r = mn1;
#pragma unroll
        for (int j=0;j<8;j++){
            oacc[j][0]*=c0; oacc[j][1]*=c0; oacc[j][2]*=c1; oacc[j][3]*=c1;
        }

#pragma unroll
        for (int s=0;s<4;s++){
            u32 ph[4], pl[4];
            split_pack(sc[2*s  ][0], sc[2*s  ][1], ph[0], pl[0]);
            split_pack(sc[2*s  ][2], sc[2*s  ][3], ph[1], pl[1]);
            split_pack(sc[2*s+1][0], sc[2*s+1][1], ph[2], pl[2]);
            split_pack(sc[2*s+1][2], sc[2*s+1][3], ph[3], pl[3]);
#pragma unroll
            for (int p=0;p<4;p++){
                int nb = p*16 + ((lane>>4)<<3) + (lane&7);
                u32 w = vbase + nb*AS + s*8 + ((lane>>3)&1)*4;
                u32 bh[4], bl[4];
                ldsm4(bh[0],bh[1],bh[2],bh[3], smb + w*4);
                ldsm4(bl[0],bl[1],bl[2],bl[3], smb + (w+KVW)*4);
                mma3(oacc[2*p  ], ph, pl, bh+0, bl+0);
                mma3(oacc[2*p+1], ph, pl, bh+2, bl+2);
            }
        }
        __syncthreads();
    }

    float inv0 = 1.f/l0r, inv1 = 1.f/l1r;
    int r0 = q0 + row + g, r1 = r0+8;
#pragma unroll
    for (int j=0;j<8;j++){
        int col = h*DKH + j*8 + t4*2;
        u32 hh, ll;
        split_pack(oacc[j][0]*inv0, oacc[j][1]*inv0, hh, ll);
        ((u32*)Ch)[(r0*NHID + col)>>1] = hh;
        ((u32*)Cl)[(r0*NHID + col)>>1] = ll;
        split_pack(oacc[j][2]*inv1, oacc[j][3]*inv1, hh, ll);
        ((u32*)Ch)[(r1*NHID + col)>>1] = hh;
        ((u32*)Cl)[(r1*NHID + col)>>1] = ll;
    }
}

// ---------------------------------------------------------------------------
extern "C" void kernel_launch(void* const* d_in, const int* in_sizes, int n_in,
                              void* d_out, int out_size)
{
    const float* Q  = (const float*)d_in[0];
    const float* K  = (const float*)d_in[1];
    const float* V  = (const float*)d_in[2];
    const float* Wq = (const float*)d_in[3];
    const float* bq = (const float*)d_in[4];
    const float* Wk = (const float*)d_in[5];
    const float* bk = (const float*)d_in[6];
    const float* Wv = (const float*)d_in[7];
    const float* bv = (const float*)d_in[8];
    const float* Wo = (const float*)d_in[9];
    const float* bo = (const float*)d_in[10];
    float* out = (float*)d_out;

    u16 *xh,*xl,*wth,*wtl,*woth,*wotl;
    u16 *qh,*ql,*kh,*kl,*vth,*vtl,*ch,*cl;
    cudaGetSymbolAddress((void**)&xh,   g_xh);
    cudaGetSymbolAddress((void**)&xl,   g_xl);
    cudaGetSymbolAddress((void**)&wth,  g_wth);
    cudaGetSymbolAddress((void**)&wtl,  g_wtl);
    cudaGetSymbolAddress((void**)&woth, g_woth);
    cudaGetSymbolAddress((void**)&wotl, g_wotl);
    cudaGetSymbolAddress((void**)&qh,   g_qh);
    cudaGetSymbolAddress((void**)&ql,   g_ql);
    cudaGetSymbolAddress((void**)&kh,   g_kh);
    cudaGetSymbolAddress((void**)&kl,   g_kl);
    cudaGetSymbolAddress((void**)&vth,  g_vth);
    cudaGetSymbolAddress((void**)&vtl,  g_vtl);
    cudaGetSymbolAddress((void**)&ch,   g_ch);
    cudaGetSymbolAddress((void**)&cl,   g_cl);

    cudaFuncSetAttribute(proj4_kernel,
                         cudaFuncAttributeMaxDynamicSharedMemorySize, PROJ_SMEM);
    cudaFuncSetAttribute(out2_kernel,
                         cudaFuncAttributeMaxDynamicSharedMemorySize, GEMM_SMEM);
    cudaFuncSetAttribute(attn_kernel,
                         cudaFuncAttributeMaxDynamicSharedMemorySize, ATTN_SMEM);

    // pre-passes
    asplit_kernel<<<3*SQ*DM/(256*8), 256>>>(Q, K, V, xh, xl);
    wsplit_qkv_kernel<<<dim3(32,2,48), dim3(32,32)>>>(Wq, Wk, Wv, wth, wtl);
    wsplit_wo_kernel<<<dim3(32,32), dim3(32,32)>>>(Wo, woth, wotl);

    // fused QKV projection: 128x128 tiles (2 heads per block)
    dim3 pg(NH/2, SQ/128, 3);     // (8, 16, 3)
    proj4_kernel<<<pg, 256, PROJ_SMEM>>>((u32*)xh,(u32*)xl,(u32*)wth,(u32*)wtl,
                                         bq, bk, bv,
                                         qh, ql, kh, kl, vth, vtl);

    dim3 ag(SQ/128, NH);          // (16, 16)
    attn_kernel<<<ag, 256, ATTN_SMEM>>>((u32*)qh,(u32*)ql,(u32*)kh,(u32*)kl,
                                        (u32*)vth,(u32*)vtl, ch, cl);

    dim3 og(DM/64, SQ/128);       // (16, 16)
    out2_kernel<<<og, 256, GEMM_SMEM>>>((u32*)ch,(u32*)cl,(u32*)woth,(u32*)wotl,
                                        bo, out);
}

// round 9
// speedup vs baseline: 1.0331x; 1.0331x over previous
#include <cuda_runtime.h>
#include <cuda_bf16.h>

#define SQ 2048
#define DM 1024
#define NH 16
#define DKH 64
#define NHID 1024

typedef unsigned int u32;
typedef unsigned short u16;

// ---------------- scratch planes (bf16 hi/lo) ----------------
__device__ u16 g_xh[3*SQ*DM];
__device__ u16 g_xl[3*SQ*DM];
__device__ u16 g_wth[3*NH*DKH*DM];   // [(which*16+h)*64+k][d]
__device__ u16 g_wtl[3*NH*DKH*DM];
__device__ u16 g_woth[NHID*DM];      // [n][k]
__device__ u16 g_wotl[NHID*DM];
__device__ u16 g_qh[NH*SQ*DKH];
__device__ u16 g_ql[NH*SQ*DKH];
__device__ u16 g_kh[NH*SQ*DKH];
__device__ u16 g_kl[NH*SQ*DKH];
__device__ u16 g_vth[NH*DKH*SQ];     // [h][d][s]
__device__ u16 g_vtl[NH*DKH*SQ];
__device__ u16 g_ch[SQ*NHID];
__device__ u16 g_cl[SQ*NHID];

// ---------------- helpers ----------------
__device__ __forceinline__ void split1(float x, u16& h, u16& l) {
    __nv_bfloat16 hb = __float2bfloat16(x);
    h = __bfloat16_as_ushort(hb);
    l = __bfloat16_as_ushort(__float2bfloat16(x - __bfloat162float(hb)));
}
__device__ __forceinline__ void split_pack(float x0, float x1, u32& h, u32& l) {
    u16 h0,l0,h1,l1;
    split1(x0,h0,l0); split1(x1,h1,l1);
    h = ((u32)h1<<16)|h0; l = ((u32)l1<<16)|l0;
}
__device__ __forceinline__ void mma_bf16(float* c, const u32* a, const u32* b) {
    asm volatile(
      "mma.sync.aligned.m16n8k16.row.col.f32.bf16.bf16.f32 "
      "{%0,%1,%2,%3}, {%4,%5,%6,%7}, {%8,%9}, {%0,%1,%2,%3};\n"
      : "+f"(c[0]), "+f"(c[1]), "+f"(c[2]), "+f"(c[3])
      : "r"(a[0]), "r"(a[1]), "r"(a[2]), "r"(a[3]), "r"(b[0]), "r"(b[1]));
}
__device__ __forceinline__ void mma3(float* c, const u32* ah, const u32* al,
                                     const u32* bh, const u32* bl) {
    mma_bf16(c, ah, bh);
    mma_bf16(c, ah, bl);
    mma_bf16(c, al, bh);
}
__device__ __forceinline__ void cp16(u32 dst_smem, const void* src) {
    asm volatile("cp.async.cg.shared.global [%0], [%1], 16;\n"
                 :: "r"(dst_smem), "l"(src));
}
__device__ __forceinline__ void cp_commit() {
    asm volatile("cp.async.commit_group;\n");
}
template<int N> __device__ __forceinline__ void cp_wait() {
    asm volatile("cp.async.wait_group %0;\n" :: "n"(N));
}
__device__ __forceinline__ void ldsm4(u32& r0, u32& r1, u32& r2, u32& r3, u32 saddr) {
    asm volatile("ldmatrix.sync.aligned.m8n8.x4.shared.b16 {%0,%1,%2,%3}, [%4];\n"
                 : "=r"(r0), "=r"(r1), "=r"(r2), "=r"(r3) : "r"(saddr));
}
// swizzled byte offset for 64B logical rows packed in 128B blocks:
// row r (0..127), 16B chunk c (0..3). Conflict-free for LDSM 8-row phases.
__device__ __forceinline__ u32 swz64(int r, int c) {
    return ((u32)(r>>1)<<7) | ((u32)(r&1)<<6) | ((u32)((c + (r>>1)) & 3)<<4);
}

// ---------------------------------------------------------------------------
// Pre-pass kernels (unchanged, proven)
// ---------------------------------------------------------------------------
__global__ __launch_bounds__(256) void asplit_kernel(
    const float* __restrict__ Q, const float* __restrict__ K,
    const float* __restrict__ V, u16* __restrict__ oh, u16* __restrict__ ol)
{
    size_t base = ((size_t)blockIdx.x*256 + threadIdx.x)*8;
    int which = (int)(base >> 21);
    size_t rem = base & 2097151;
    const float* in = (which==0)?Q:(which==1)?K:V;
    float4 f0 = *(const float4*)(in+rem);
    float4 f1 = *(const float4*)(in+rem+4);
    u32 h0,l0,h1,l1,h2,l2,h3,l3;
    split_pack(f0.x,f0.y,h0,l0);
    split_pack(f0.z,f0.w,h1,l1);
    split_pack(f1.x,f1.y,h2,l2);
    split_pack(f1.z,f1.w,h3,l3);
    *(uint4*)(oh + base) = make_uint4(h0,h1,h2,h3);
    *(uint4*)(ol + base) = make_uint4(l0,l1,l2,l3);
}

__global__ void wsplit_qkv_kernel(
    const float* __restrict__ Wq, const float* __restrict__ Wk,
    const float* __restrict__ Wv, u16* __restrict__ oh, u16* __restrict__ ol)
{
    __shared__ float t[32][33];
    int z = blockIdx.z, which = z>>4, h = z&15;
    const float* in = ((which==0)?Wq:(which==1)?Wk:Wv) + (size_t)h*DM*DKH;
    int d0 = blockIdx.x*32, k0 = blockIdx.y*32;
    int tx = threadIdx.x, ty = threadIdx.y;
    t[ty][tx] = in[(size_t)(d0+ty)*DKH + k0+tx];
    __syncthreads();
    float v = t[tx][ty];
    u16 hh,ll; split1(v,hh,ll);
    size_t o = ((size_t)z*DKH + k0+ty)*DM + d0+tx;
    oh[o]=hh; ol[o]=ll;
}

__global__ void wsplit_wo_kernel(
    const float* __restrict__ Wo, u16* __restrict__ oh, u16* __restrict__ ol)
{
    __shared__ float t[32][33];
    int k0 = blockIdx.x*32, n0 = blockIdx.y*32;
    int tx = threadIdx.x, ty = threadIdx.y;
    t[ty][tx] = Wo[(size_t)(k0+ty)*DM + n0+tx];
    __syncthreads();
    float v = t[tx][ty];
    u16 hh,ll; split1(v,hh,ll);
    size_t o = ((size_t)(n0+ty))*DM + k0+tx;
    oh[o]=hh; ol[o]=ll;
}

// ---------------------------------------------------------------------------
// 3-stage XOR-swizzled GEMM geometry: 128(M) x 128(N), BK=32.
// stage = Ah(8KB) Al(8KB) Bh(8KB) Bl(8KB) = 32KB; 3 stages = 96KB.
// One __syncthreads per k-tile; cp.async prefetch depth 2.
// ---------------------------------------------------------------------------
#define P5_TILE 8192
#define P5_STG  (4*P5_TILE)      // 32768 B
#define GEMM5_SMEM (3*P5_STG)    // 98304 B
#define NKT 32                   // K=1024 / BK=32

// ---- fused QKV projection ----
__global__ __launch_bounds__(256,2) void proj5_kernel(
    const u32* __restrict__ Xh, const u32* __restrict__ Xl,
    const u32* __restrict__ Wth, const u32* __restrict__ Wtl,
    const float* __restrict__ bq, const float* __restrict__ bk,
    const float* __restrict__ bv,
    u16* __restrict__ oqh, u16* __restrict__ oql,
    u16* __restrict__ okh, u16* __restrict__ okl,
    u16* __restrict__ ovh, u16* __restrict__ ovl)
{
    extern __shared__ u32 sm[];
    const u32 smb = (u32)__cvta_generic_to_shared(sm);
    const int tid = threadIdx.x, lane = tid&31, wid = tid>>5;
    const int g = lane>>2, t4 = lane&3;
    const int wm = wid>>2, wn = wid&3;       // 2x4 warps, warp tile 64x32
    const int which = blockIdx.z, head0 = blockIdx.x*2, m0 = blockIdx.y*128;

    const u32* aH = Xh + (size_t)which*(SQ*DM/2);
    const u32* aL = Xl + (size_t)which*(SQ*DM/2);
    const int zrow = (which*NH + head0)*DKH;

    float acc[4][4][4];
#pragma unroll
    for (int i=0;i<4;i++)
#pragma unroll
      for (int j=0;j<4;j++)
#pragma unroll
        for (int e=0;e<4;e++) acc[i][j][e]=0.f;

    auto issue = [&](int kt){
        if (kt < NKT){
            u32 base = (kt%3)*P5_STG;
#pragma unroll
            for (int j=0;j<8;j++){
                int i = tid + j*256;
                int tile = i>>9, rem = i&511;
                int r = rem>>2, c = rem&3;
                const u32* src;
                if      (tile==0) src = aH  + (size_t)(m0+r)*512   + kt*16 + c*4;
                else if (tile==1) src = aL  + (size_t)(m0+r)*512   + kt*16 + c*4;
                else if (tile==2) src = Wth + (size_t)(zrow+r)*512 + kt*16 + c*4;
                else              src = Wtl + (size_t)(zrow+r)*512 + kt*16 + c*4;
                cp16(smb + base + tile*P5_TILE + swz64(r,c), src);
            }
        }
        cp_commit();
    };

    issue(0); issue(1);
    for (int kt=0; kt<NKT; kt++){
        cp_wait<1>();
        __syncthreads();
        issue(kt+2);

        u32 base = smb + (kt%3)*P5_STG;
#pragma unroll
        for (int ks=0; ks<2; ks++){
            u32 bh[2][4], bl[2][4];
#pragma unroll
            for (int p=0;p<2;p++){
                int nb = wn*32 + p*16 + ((lane>>4)<<3) + (lane&7);
                int cB = ks*2 + ((lane>>3)&1);
                u32 w = base + 2*P5_TILE + swz64(nb, cB);
                ldsm4(bh[p][0],bh[p][1],bh[p][2],bh[p][3], w);
                ldsm4(bl[p][0],bl[p][1],bl[p][2],bl[p][3], w + P5_TILE);
            }
#pragma unroll
            for (int i=0;i<4;i++){
                int rowb = wm*64 + i*16 + (lane&15);
                int cA = ks*2 + (lane>>4);
                u32 w = base + swz64(rowb, cA);
                u32 ah[4], al[4];
                ldsm4(ah[0],ah[1],ah[2],ah[3], w);
                ldsm4(al[0],al[1],al[2],al[3], w + P5_TILE);
#pragma unroll
                for (int p=0;p<2;p++){
                    mma3(acc[i][2*p  ], ah, al, bh[p]+0, bl[p]+0);
                    mma3(acc[i][2*p+1], ah, al, bh[p]+2, bl[p]+2);
                }
            }
        }
    }

    // epilogue (identical math to proven proj4)
    const float* bias = (which==0)?bq:(which==1)?bk:bv;
    const int transposed = (which==2);
    const float osc = (which==0)?0.125f:1.f;
#pragma unroll
    for (int i=0;i<4;i++){
#pragma unroll
        for (int j=0;j<4;j++){
            int r0 = m0 + wm*64 + i*16 + g;
            int r1 = r0 + 8;
            int ncol = wn*32 + j*8 + t4*2;
            int head = head0 + (ncol>>6);
            int dc = ncol & 63;
            float b0f = bias[head*DKH + dc];
            float b1f = bias[head*DKH + dc + 1];
            float v0 = (acc[i][j][0] + b0f) * osc;
            float v1 = (acc[i][j][1] + b1f) * osc;
            float v2 = (acc[i][j][2] + b0f) * osc;
            float v3 = (acc[i][j][3] + b1f) * osc;
            if (!transposed) {
                u16* outH = (which==0)?oqh:okh;
                u16* outL = (which==0)?oql:okl;
                u32 h,l;
                split_pack(v0,v1,h,l);
                ((u32*)outH)[(head*SQ + r0)*32 + (dc>>1)] = h;
                ((u32*)outL)[(head*SQ + r0)*32 + (dc>>1)] = l;
                split_pack(v2,v3,h,l);
                ((u32*)outH)[(head*SQ + r1)*32 + (dc>>1)] = h;
                ((u32*)outL)[(head*SQ + r1)*32 + (dc>>1)] = l;
            } else {
                u16 h,l;
                split1(v0,h,l); ovh[(head*DKH+dc  )*SQ + r0]=h; ovl[(head*DKH+dc  )*SQ + r0]=l;
                split1(v1,h,l); ovh[(head*DKH+dc+1)*SQ + r0]=h; ovl[(head*DKH+dc+1)*SQ + r0]=l;
                split1(v2,h,l); ovh[(head*DKH+dc  )*SQ + r1]=h; ovl[(head*DKH+dc  )*SQ + r1]=l;
                split1(v3,h,l); ovh[(head*DKH+dc+1)*SQ + r1]=h; ovl[(head*DKH+dc+1)*SQ + r1]=l;
            }
        }
    }
}

// ---- output projection, same 3-stage structure, 128x128 tile ----
__global__ __launch_bounds__(256,2) void out5_kernel(
    const u32* __restrict__ Ah, const u32* __restrict__ Al,
    const u32* __restrict__ Bh, const u32* __restrict__ Bl,
    const float* __restrict__ bias, float* __restrict__ C)
{
    extern __shared__ u32 sm[];
    const u32 smb = (u32)__cvta_generic_to_shared(sm);
    const int tid = threadIdx.x, lane = tid&31, wid = tid>>5;
    const int g = lane>>2, t4 = lane&3;
    const int wm = wid>>2, wn = wid&3;
    const int n0 = blockIdx.x*128, m0 = blockIdx.y*128;

    float acc[4][4][4];
#pragma unroll
    for (int i=0;i<4;i++)
#pragma unroll
      for (int j=0;j<4;j++)
#pragma unroll
        for (int e=0;e<4;e++) acc[i][j][e]=0.f;

    auto issue = [&](int kt){
        if (kt < NKT){
            u32 base = (kt%3)*P5_STG;
#pragma unroll
            for (int j=0;j<8;j++){
                int i = tid + j*256;
                int tile = i>>9, rem = i&511;
                int r = rem>>2, c = rem&3;
                const u32* src;
                if      (tile==0) src = Ah + (size_t)(m0+r)*512 + kt*16 + c*4;
                else if (tile==1) src = Al + (size_t)(m0+r)*512 + kt*16 + c*4;
                else if (tile==2) src = Bh + (size_t)(n0+r)*512 + kt*16 + c*4;
                else              src = Bl + (size_t)(n0+r)*512 + kt*16 + c*4;
                cp16(smb + base + tile*P5_TILE + swz64(r,c), src);
            }
        }
        cp_commit();
    };

    issue(0); issue(1);
    for (int kt=0; kt<NKT; kt++){
        cp_wait<1>();
        __syncthreads();
        issue(kt+2);

        u32 base = smb + (kt%3)*P5_STG;
#pragma unroll
        for (int ks=0; ks<2; ks++){
            u32 bh[2][4], bl[2][4];
#pragma unroll
            for (int p=0;p<2;p++){
                int nb = wn*32 + p*16 + ((lane>>4)<<3) + (lane&7);
                int cB = ks*2 + ((lane>>3)&1);
                u32 w = base + 2*P5_TILE + swz64(nb, cB);
                ldsm4(bh[p][0],bh[p][1],bh[p][2],bh[p][3], w);
                ldsm4(bl[p][0],bl[p][1],bl[p][2],bl[p][3], w + P5_TILE);
            }
#pragma unroll
            for (int i=0;i<4;i++){
                int rowb = wm*64 + i*16 + (lane&15);
                int cA = ks*2 + (lane>>4);
                u32 w = base + swz64(rowb, cA);
                u32 ah[4], al[4];
                ldsm4(ah[0],ah[1],ah[2],ah[3], w);
                ldsm4(al[0],al[1],al[2],al[3], w + P5_TILE);
#pragma unroll
                for (int p=0;p<2;p++){
                    mma3(acc[i][2*p  ], ah, al, bh[p]+0, bl[p]+0);
                    mma3(acc[i][2*p+1], ah, al, bh[p]+2, bl[p]+2);
                }
            }
        }
    }

#pragma unroll
    for (int i=0;i<4;i++){
#pragma unroll
        for (int j=0;j<4;j++){
            int r0 = m0 + wm*64 + i*16 + g;
            int r1 = r0 + 8;
            int col = n0 + wn*32 + j*8 + t4*2;
            C[(size_t)r0*DM + col    ] = acc[i][j][0] + bias[col];
            C[(size_t)r0*DM + col + 1] = acc[i][j][1] + bias[col+1];
            C[(size_t)r1*DM + col    ] = acc[i][j][2] + bias[col];
            C[(size_t)r1*DM + col + 1] = acc[i][j][3] + bias[col+1];
        }
    }
}

// ---------------------------------------------------------------------------
// Flash attention (proven round-6 version, unchanged)
// ---------------------------------------------------------------------------
#define AS 36
#define KVW (64*AS)
#define ATTN_WORDS (2*128*AS + 2*4*KVW)
#define ATTN_SMEM (ATTN_WORDS*4)

__global__ __launch_bounds__(256,2) void attn_kernel(
    const u32* __restrict__ Qh, const u32* __restrict__ Ql,
    const u32* __restrict__ Kh, const u32* __restrict__ Kl,
    const u32* __restrict__ Vh, const u32* __restrict__ Vl,
    u16* __restrict__ Ch, u16* __restrict__ Cl)
{
    extern __shared__ u32 sm[];
    const u32 smb = (u32)__cvta_generic_to_shared(sm);

    const int tid = threadIdx.x, lane = tid&31, wid = tid>>5;
    const int g = lane>>2, t4 = lane&3;
    const int h = blockIdx.y, q0 = blockIdx.x*128;
    const int row = wid*16;

#pragma unroll
    for (int j=0;j<8;j++){
        int i = tid + j*256;
        int plane = i>>10, rem = i&1023;
        int r = rem>>3, c = rem&7;
        const u32* src = (plane ? Ql : Qh) + ((size_t)(h*SQ + q0 + r))*32 + c*4;
        cp16(smb + ((plane ? 128*AS : 0) + r*AS + c*4)*4, src);
    }
    cp_commit();

    auto issueKV = [&](int t, int st){
        u32 base = 2*128*AS + st*4*KVW;
#pragma unroll
        for (int j=0;j<2;j++){
            int i = tid + j*256;
            int r = i>>3, c = i&7;
            cp16(smb + (base +           r*AS + c*4)*4, Kh + ((size_t)(h*SQ + t*64 + r))*32 + c*4);
            cp16(smb + (base +   KVW +   r*AS + c*4)*4, Kl + ((size_t)(h*SQ + t*64 + r))*32 + c*4);
            cp16(smb + (base + 2*KVW +   r*AS + c*4)*4, Vh + ((size_t)(h*DKH + r))*1024 + t*32 + c*4);
            cp16(smb + (base + 3*KVW +   r*AS + c*4)*4, Vl + ((size_t)(h*DKH + r))*1024 + t*32 + c*4);
        }
        cp_commit();
    };
    issueKV(0,0);

    float oacc[8][4];
#pragma unroll
    for (int j=0;j<8;j++)
#pragma unroll
        for (int e=0;e<4;e++) oacc[j][e]=0.f;
    float m0r=-1e30f, m1r=-1e30f, l0r=0.f, l1r=0.f;

    for (int t=0; t<SQ/64; t++){
        const int st = t & 1;
        if (t+1 < SQ/64) { issueKV(t+1, st^1); cp_wait<1>(); }
        else cp_wait<0>();
        __syncthreads();

        u32 kbase = 2*128*AS + st*4*KVW;
        u32 vbase = kbase + 2*KVW;

        float sc[8][4];
#pragma unroll
        for (int j=0;j<8;j++)
#pragma unroll
            for (int e=0;e<4;e++) sc[j][e]=0.f;
#pragma unroll
        for (int ks=0;ks<4;ks++){
            u32 qh[4], ql[4];
            int rowb = row + (lane&15);
            u32 wq = rowb*AS + ks*8 + (lane>>4)*4;
            ldsm4(qh[0],qh[1],qh[2],qh[3], smb + wq*4);
            ldsm4(ql[0],ql[1],ql[2],ql[3], smb + (wq + 128*AS)*4);
#pragma unroll
            for (int p=0;p<4;p++){
                int nb = p*16 + ((lane>>4)<<3) + (lane&7);
                u32 w = kbase + nb*AS + ks*8 + ((lane>>3)&1)*4;
                u32 bh[4], bl[4];
                ldsm4(bh[0],bh[1],bh[2],bh[3], smb + w*4);
                ldsm4(bl[0],bl[1],bl[2],bl[3], smb + (w+KVW)*4);
                mma3(sc[2*p  ], qh, ql, bh+0, bl+0);
                mma3(sc[2*p+1], qh, ql, bh+2, bl+2);
            }
        }

        float tm0=-1e30f, tm1=-1e30f;
#pragma unroll
        for (int j=0;j<8;j++){
            tm0 = fmaxf(tm0, fmaxf(sc[j][0], sc[j][1]));
            tm1 = fmaxf(tm1, fmaxf(sc[j][2], sc[j][3]));
        }
        tm0 = fmaxf(tm0, __shfl_xor_sync(0xffffffffu, tm0, 1));
        tm0 = fmaxf(tm0, __shfl_xor_sync(0xffffffffu, tm0, 2));
        tm1 = fmaxf(tm1, __shfl_xor_sync(0xffffffffu, tm1, 1));
        tm1 = fmaxf(tm1, __shfl_xor_sync(0xffffffffu, tm1, 2));
        float mn0 = fmaxf(m0r, tm0), mn1 = fmaxf(m1r, tm1);
        float c0 = __expf(m0r - mn0), c1 = __expf(m1r - mn1);
        float rs0=0.f, rs1=0.f;
#pragma unroll
        for (int j=0;j<8;j++){
            sc[j][0]=__expf(sc[j][0]-mn0); sc[j][1]=__expf(sc[j][1]-mn0);
            sc[j][2]=__expf(sc[j][2]-mn1); sc[j][3]=__expf(sc[j][3]-mn1);
            rs0 += sc[j][0]+sc[j][1]; rs1 += sc[j][2]+sc[j][3];
        }
        rs0 += __shfl_xor_sync(0xffffffffu, rs0, 1);
        rs0 += __shfl_xor_sync(0xffffffffu, rs0, 2);
        rs1 += __shfl_xor_sync(0xffffffffu, rs1, 1);
        rs1 += __shfl_xor_sync(0xffffffffu, rs1, 2);
        l0r = l0r*c0 + rs0; l1r = l1r*c1 + rs1;
        m0r = mn0; m1r = mn1;
#pragma unroll
        for (int j=0;j<8;j++){
            oacc[j][0]*=c0; oacc[j][1]*=c0; oacc[j][2]*=c1; oacc[j][3]*=c1;
        }

#pragma unroll
        for (int s=0;s<4;s++){
            u32 ph[4], pl[4];
            split_pack(sc[2*s  ][0], sc[2*s  ][1], ph[0], pl[0]);
            split_pack(sc[2*s  ][2], sc[2*s  ][3], ph[1], pl[1]);
            split_pack(sc[2*s+1][0], sc[2*s+1][1], ph[2], pl[2]);
            split_pack(sc[2*s+1][2], sc[2*s+1][3], ph[3], pl[3]);
#pragma unroll
            for (int p=0;p<4;p++){
                int nb = p*16 + ((lane>>4)<<3) + (lane&7);
                u32 w = vbase + nb*AS + s*8 + ((lane>>3)&1)*4;
                u32 bh[4], bl[4];
                ldsm4(bh[0],bh[1],bh[2],bh[3], smb + w*4);
                ldsm4(bl[0],bl[1],bl[2],bl[3], smb + (w+KVW)*4);
                mma3(oacc[2*p  ], ph, pl, bh+0, bl+0);
                mma3(oacc[2*p+1], ph, pl, bh+2, bl+2);
            }
        }
        __syncthreads();
    }

    float inv0 = 1.f/l0r, inv1 = 1.f/l1r;
    int r0 = q0 + row + g, r1 = r0+8;
#pragma unroll
    for (int j=0;j<8;j++){
        int col = h*DKH + j*8 + t4*2;
        u32 hh, ll;
        split_pack(oacc[j][0]*inv0, oacc[j][1]*inv0, hh, ll);
        ((u32*)Ch)[(r0*NHID + col)>>1] = hh;
        ((u32*)Cl)[(r0*NHID + col)>>1] = ll;
        split_pack(oacc[j][2]*inv1, oacc[j][3]*inv1, hh, ll);
        ((u32*)Ch)[(r1*NHID + col)>>1] = hh;
        ((u32*)Cl)[(r1*NHID + col)>>1] = ll;
    }
}

// ---------------------------------------------------------------------------
extern "C" void kernel_launch(void* const* d_in, const int* in_sizes, int n_in,
                              void* d_out, int out_size)
{
    const float* Q  = (const float*)d_in[0];
    const float* K  = (const float*)d_in[1];
    const float* V  = (const float*)d_in[2];
    const float* Wq = (const float*)d_in[3];
    const float* bq = (const float*)d_in[4];
    const float* Wk = (const float*)d_in[5];
    const float* bk = (const float*)d_in[6];
    const float* Wv = (const float*)d_in[7];
    const float* bv = (const float*)d_in[8];
    const float* Wo = (const float*)d_in[9];
    const float* bo = (const float*)d_in[10];
    float* out = (float*)d_out;

    u16 *xh,*xl,*wth,*wtl,*woth,*wotl;
    u16 *qh,*ql,*kh,*kl,*vth,*vtl,*ch,*cl;
    cudaGetSymbolAddress((void**)&xh,   g_xh);
    cudaGetSymbolAddress((void**)&xl,   g_xl);
    cudaGetSymbolAddress((void**)&wth,  g_wth);
    cudaGetSymbolAddress((void**)&wtl,  g_wtl);
    cudaGetSymbolAddress((void**)&woth, g_woth);
    cudaGetSymbolAddress((void**)&wotl, g_wotl);
    cudaGetSymbolAddress((void**)&qh,   g_qh);
    cudaGetSymbolAddress((void**)&ql,   g_ql);
    cudaGetSymbolAddress((void**)&kh,   g_kh);
    cudaGetSymbolAddress((void**)&kl,   g_kl);
    cudaGetSymbolAddress((void**)&vth,  g_vth);
    cudaGetSymbolAddress((void**)&vtl,  g_vtl);
    cudaGetSymbolAddress((void**)&ch,   g_ch);
    cudaGetSymbolAddress((void**)&cl,   g_cl);

    cudaFuncSetAttribute(proj5_kernel,
                         cudaFuncAttributeMaxDynamicSharedMemorySize, GEMM5_SMEM);
    cudaFuncSetAttribute(out5_kernel,
                         cudaFuncAttributeMaxDynamicSharedMemorySize, GEMM5_SMEM);
    cudaFuncSetAttribute(attn_kernel,
                         cudaFuncAttributeMaxDynamicSharedMemorySize, ATTN_SMEM);

    // pre-passes
    asplit_kernel<<<3*SQ*DM/(256*8), 256>>>(Q, K, V, xh, xl);
    wsplit_qkv_kernel<<<dim3(32,2,48), dim3(32,32)>>>(Wq, Wk, Wv, wth, wtl);
    wsplit_wo_kernel<<<dim3(32,32), dim3(32,32)>>>(Wo, woth, wotl);

    // fused QKV projection: 128x128 tiles, 3-stage pipeline
    dim3 pg(NH/2, SQ/128, 3);     // (8, 16, 3)
    proj5_kernel<<<pg, 256, GEMM5_SMEM>>>((u32*)xh,(u32*)xl,(u32*)wth,(u32*)wtl,
                                          bq, bk, bv,
                                          qh, ql, kh, kl, vth, vtl);

    dim3 ag(SQ/128, NH);          // (16, 16)
    attn_kernel<<<ag, 256, ATTN_SMEM>>>((u32*)qh,(u32*)ql,(u32*)kh,(u32*)kl,
                                        (u32*)vth,(u32*)vtl, ch, cl);

    dim3 og(DM/128, SQ/128);      // (8, 16)
    out5_kernel<<<og, 256, GEMM5_SMEM>>>((u32*)ch,(u32*)cl,(u32*)woth,(u32*)wotl,
                                         bo, out);
}